// round 1
// baseline (speedup 1.0000x reference)
#include <cuda_runtime.h>

#define NMAX 100000
#define REC4 24            // float4 chunks per node record (96 floats)
#define LPB  16            // loops per block in k_loops

// Scratch (static __device__ — no runtime allocation)
__device__ float4 g_pre[(size_t)NMAX * REC4];   // per-node: q*invsqrt8[16], k[16], wfold[2][32]
__device__ float  g_M[32 * 16];                 // fc_w @ out_proj_w
__device__ float  g_b32[32];                    // fc_w @ out_proj_b + fc_b
__device__ int    g_idx64;                      // 1 if stroke_to_loop is int64

// smem swizzle: spread the 4 loop-groups of a warp (and l/m) across banks.
// key = (m ^ ll) & 3 flips the low 16B-chunk bits within each 64B region.
#define SWZ(slot, c) (((slot) * REC4) + ((c) ^ (((slot) ^ ((slot) >> 3)) & 3)))

__device__ __forceinline__ int fetch_idx(const void* p, long long i, int is64) {
    if (is64) return (int)__ldg((const long long*)p + i);
    return __ldg((const int*)p + i);
}

__device__ __forceinline__ unsigned long long pk2(float lo, float hi) {
    unsigned long long r;
    asm("mov.b64 %0, {%1, %2};" : "=l"(r) : "f"(lo), "f"(hi));
    return r;
}
__device__ __forceinline__ void upk2(unsigned long long v, float& lo, float& hi) {
    asm("mov.b64 {%0, %1}, %2;" : "=f"(lo), "=f"(hi) : "l"(v));
}
// packed fp32x2 FMA (sm_100): d = a*b + d per 32-bit half
__device__ __forceinline__ void ffma2(unsigned long long& d, unsigned long long a, unsigned long long b) {
    asm("fma.rn.f32x2 %0, %1, %2, %0;" : "+l"(d) : "l"(a), "l"(b));
}

// ---------------- Kernel 0: fold weights + index dtype detection ----------------
__global__ void k_prep(const float* __restrict__ fc_w,
                       const float* __restrict__ out_proj_w,
                       const float* __restrict__ out_proj_b,
                       const float* __restrict__ fc_b,
                       const int* __restrict__ idx_raw) {
    int t = threadIdx.x;
    if (t < 512) {
        int o = t >> 4, e = t & 15;
        float acc = 0.f;
        #pragma unroll
        for (int j = 0; j < 16; j++) acc += fc_w[o * 16 + j] * out_proj_w[j * 16 + e];
        g_M[o * 16 + e] = acc;
    }
    if (t < 32) {
        float acc = fc_b[t];
        #pragma unroll
        for (int j = 0; j < 16; j++) acc += fc_w[t * 16 + j] * out_proj_b[j];
        g_b32[t] = acc;
    }
    if (t == 0) {
        // int64 indices (<2^31) => every odd int32 word is zero
        int nz = 0;
        for (int i = 1; i < 256; i += 2) nz += (idx_raw[i] != 0);
        g_idx64 = (nz == 0) ? 1 : 0;
    }
}

// ---------------- Kernel 1: per-node precompute ----------------
__global__ void __launch_bounds__(128)
k_node(const float* __restrict__ nf,
       const float* __restrict__ w1, const float* __restrict__ b1,
       const float* __restrict__ w2, const float* __restrict__ b2,
       const float* __restrict__ wp, const float* __restrict__ bp,
       int N) {
    int n = blockIdx.x * blockDim.x + threadIdx.x;
    if (n >= N) return;

    float f[6];
    #pragma unroll
    for (int i = 0; i < 6; i++) f[i] = __ldg(nf + (size_t)n * 6 + i);

    float h[32];
    #pragma unroll
    for (int o = 0; o < 32; o++) {
        float a = __ldg(b1 + o);
        #pragma unroll
        for (int i = 0; i < 6; i++) a += __ldg(w1 + o * 6 + i) * f[i];
        h[o] = fmaxf(a, 0.f);
    }
    float x[16];
    #pragma unroll
    for (int e = 0; e < 16; e++) {
        float a = __ldg(b2 + e);
        #pragma unroll
        for (int i = 0; i < 32; i++) a += __ldg(w2 + e * 32 + i) * h[i];
        x[e] = a;
    }
    float qkv[48];
    #pragma unroll
    for (int o = 0; o < 48; o++) {
        float a = __ldg(bp + o);
        #pragma unroll
        for (int e = 0; e < 16; e++) a += __ldg(wp + o * 16 + e) * x[e];
        qkv[o] = a;
    }

    float4* rec4 = g_pre + (size_t)n * REC4;
    const float s = 0.3535533905932738f;  // 1/sqrt(8): fold score scale into q
    #pragma unroll
    for (int j = 0; j < 4; j++)
        rec4[j] = make_float4(qkv[4 * j] * s, qkv[4 * j + 1] * s, qkv[4 * j + 2] * s, qkv[4 * j + 3] * s);
    #pragma unroll
    for (int j = 0; j < 4; j++)
        rec4[4 + j] = make_float4(qkv[16 + 4 * j], qkv[17 + 4 * j], qkv[18 + 4 * j], qkv[19 + 4 * j]);

    // wfold[h][o] = sum_d v[h*8+d] * M[o][h*8+d]
    #pragma unroll
    for (int h2 = 0; h2 < 2; h2++) {
        #pragma unroll
        for (int j = 0; j < 8; j++) {
            float wv[4];
            #pragma unroll
            for (int c = 0; c < 4; c++) {
                int o = 4 * j + c;
                float a = 0.f;
                #pragma unroll
                for (int d = 0; d < 8; d++) a += qkv[32 + h2 * 8 + d] * g_M[o * 16 + h2 * 8 + d];
                wv[c] = a;
            }
            rec4[8 + h2 * 8 + j] = make_float4(wv[0], wv[1], wv[2], wv[3]);
        }
    }
}

// ---------------- Kernel 2: per-loop attention + epilogue ----------------
__global__ void __launch_bounds__(128, 4)
k_loops(const void* __restrict__ s2l,
        const float* __restrict__ fco_w, const float* __restrict__ fco_b,
        float* __restrict__ out, int B) {
    __shared__ float4 s_data4[LPB * 8 * REC4];  // 48 KB exactly

    const int tid = threadIdx.x;
    const long long base8 = (long long)blockIdx.x * (LPB * 8);
    const long long total8 = (long long)B * 8;
    const int is64 = g_idx64;

    // ---- stage 128 stroke records (swizzled) ----
    #pragma unroll
    for (int it = 0; it < 24; it++) {
        int i = tid + it * 128;          // 0..3071
        int slot = i / 24;
        int c = i - slot * 24;
        long long gi = base8 + slot;
        if (gi >= total8) gi = 0;
        int node = fetch_idx(s2l, gi, is64);
        s_data4[SWZ(slot, c)] = __ldg((const float4*)g_pre + (size_t)node * REC4 + c);
    }
    __syncthreads();

    const int ll = tid >> 3;   // loop within block
    const int l = tid & 7;     // query row
    const int slot_l = ll * 8 + l;

    // ---- q (prescaled) ----
    float q[16];
    {
        float4 a = s_data4[SWZ(slot_l, 0)], b = s_data4[SWZ(slot_l, 1)];
        float4 c = s_data4[SWZ(slot_l, 2)], d = s_data4[SWZ(slot_l, 3)];
        q[0] = a.x; q[1] = a.y; q[2] = a.z; q[3] = a.w;
        q[4] = b.x; q[5] = b.y; q[6] = b.z; q[7] = b.w;
        q[8] = c.x; q[9] = c.y; q[10] = c.z; q[11] = c.w;
        q[12] = d.x; q[13] = d.y; q[14] = d.z; q[15] = d.w;
    }

    // ---- scores (both heads) ----
    float p0[8], p1[8];
    #pragma unroll
    for (int m = 0; m < 8; m++) {
        int sm = ll * 8 + m;
        float4 k0 = s_data4[SWZ(sm, 4)], k1 = s_data4[SWZ(sm, 5)];
        float4 k2 = s_data4[SWZ(sm, 6)], k3 = s_data4[SWZ(sm, 7)];
        p0[m] = q[0] * k0.x + q[1] * k0.y + q[2] * k0.z + q[3] * k0.w +
                q[4] * k1.x + q[5] * k1.y + q[6] * k1.z + q[7] * k1.w;
        p1[m] = q[8] * k2.x + q[9] * k2.y + q[10] * k2.z + q[11] * k2.w +
                q[12] * k3.x + q[13] * k3.y + q[14] * k3.z + q[15] * k3.w;
    }

    // ---- softmax over m, per head ----
    {
        float mx0 = p0[0], mx1 = p1[0];
        #pragma unroll
        for (int m = 1; m < 8; m++) { mx0 = fmaxf(mx0, p0[m]); mx1 = fmaxf(mx1, p1[m]); }
        float s0 = 0.f, s1 = 0.f;
        #pragma unroll
        for (int m = 0; m < 8; m++) {
            p0[m] = __expf(p0[m] - mx0); s0 += p0[m];
            p1[m] = __expf(p1[m] - mx1); s1 += p1[m];
        }
        float i0 = __frcp_rn(s0), i1 = __frcp_rn(s1);
        #pragma unroll
        for (int m = 0; m < 8; m++) { p0[m] *= i0; p1[m] *= i1; }
    }

    // ---- z[o] = sum_h sum_m p[h][m] * wfold_m[h][o], packed f32x2 FMAs ----
    unsigned long long z2[16];
    #pragma unroll
    for (int j = 0; j < 16; j++) z2[j] = 0ULL;
    #pragma unroll
    for (int m = 0; m < 8; m++) {
        int sm = ll * 8 + m;
        unsigned long long pp0 = pk2(p0[m], p0[m]);
        unsigned long long pp1 = pk2(p1[m], p1[m]);
        #pragma unroll
        for (int j = 0; j < 8; j++) {
            ulonglong2 wv = *reinterpret_cast<const ulonglong2*>(s_data4 + SWZ(sm, 8 + j));
            ffma2(z2[2 * j], pp0, wv.x);
            ffma2(z2[2 * j + 1], pp0, wv.y);
        }
        #pragma unroll
        for (int j = 0; j < 8; j++) {
            ulonglong2 wv = *reinterpret_cast<const ulonglong2*>(s_data4 + SWZ(sm, 16 + j));
            ffma2(z2[2 * j], pp1, wv.x);
            ffma2(z2[2 * j + 1], pp1, wv.y);
        }
    }

    // ---- t = relu(z + bias32); butterfly-sum over the 8 query rows ----
    float t[32];
    #pragma unroll
    for (int j = 0; j < 16; j++) {
        float lo, hi;
        upk2(z2[j], lo, hi);
        t[2 * j] = lo; t[2 * j + 1] = hi;
    }
    #pragma unroll
    for (int o = 0; o < 32; o++) t[o] = fmaxf(t[o] + g_b32[o], 0.f);
    #pragma unroll
    for (int st = 0; st < 3; st++) {
        int mask = 1 << st;  // 1,2,4 — stays within each 8-lane loop group
        #pragma unroll
        for (int o = 0; o < 32; o++) t[o] += __shfl_xor_sync(0xffffffffu, t[o], mask);
    }
    #pragma unroll
    for (int o = 0; o < 32; o++) t[o] *= 0.125f;  // mean over L=8

    // ---- fco: each of 8 lanes computes 4 outputs ----
    float r[4];
    #pragma unroll
    for (int jj = 0; jj < 4; jj++) {
        int o2 = l * 4 + jj;
        float a = __ldg(fco_b + o2);
        #pragma unroll
        for (int i = 0; i < 32; i++) a += __ldg(fco_w + o2 * 32 + i) * t[i];
        r[jj] = a;
    }

    long long lg = (long long)blockIdx.x * LPB + ll;
    if (lg < B)
        reinterpret_cast<float4*>(out)[lg * 8 + l] = make_float4(r[0], r[1], r[2], r[3]);
}

// ---------------- launch ----------------
extern "C" void kernel_launch(void* const* d_in, const int* in_sizes, int n_in,
                              void* d_out, int out_size) {
    const float* node_features = (const float*)d_in[0];
    const void*  stroke_to_loop = d_in[1];
    const float* fc1_w = (const float*)d_in[2];
    const float* fc1_b = (const float*)d_in[3];
    const float* fc2_w = (const float*)d_in[4];
    const float* fc2_b = (const float*)d_in[5];
    const float* in_proj_w = (const float*)d_in[6];
    const float* in_proj_b = (const float*)d_in[7];
    const float* out_proj_w = (const float*)d_in[8];
    const float* out_proj_b = (const float*)d_in[9];
    const float* fc_w = (const float*)d_in[10];
    const float* fc_b = (const float*)d_in[11];
    const float* fco_w = (const float*)d_in[12];
    const float* fco_b = (const float*)d_in[13];

    int N = in_sizes[0] / 6;
    int B = in_sizes[1] / 8;

    k_prep<<<1, 512>>>(fc_w, out_proj_w, out_proj_b, fc_b, (const int*)stroke_to_loop);
    k_node<<<(N + 127) / 128, 128>>>(node_features, fc1_w, fc1_b, fc2_w, fc2_b,
                                     in_proj_w, in_proj_b, N);
    k_loops<<<(B + LPB - 1) / LPB, 128>>>(stroke_to_loop, fco_w, fco_b, (float*)d_out, B);
}

// round 2
// speedup vs baseline: 1.5275x; 1.5275x over previous
#include <cuda_runtime.h>

#define NMAX 100000
#define GREC 24            // float4 chunks per node record in GMEM (96 floats)
#define CH   20            // float4 chunks per slot in SMEM (k + wfold, q excluded)
#define LPB  16            // loops per block in k_loops

// Scratch (static __device__ — no runtime allocation)
__device__ float4 g_pre[(size_t)NMAX * GREC];   // per-node: q*invsqrt8[16], k[16], wfold[2][32]
__device__ float  g_M[32 * 16];                 // fc_w @ out_proj_w
__device__ float  g_b32[32];                    // fc_w @ out_proj_b + fc_b
__device__ int    g_idx64;                      // 1 if stroke_to_loop is int64

// chunk swizzle inside a slot: key distinct across the 4 loop-groups of a warp
#define SKEY(slot) (((slot) ^ ((slot) >> 3)) & 3)
// fco row swizzle: key injective over the 8 lanes of a loop group
#define FKEY(o) ((((o) ^ ((o) >> 2))) & 7)

__device__ __forceinline__ int fetch_idx(const void* p, long long i, int is64) {
    if (is64) return (int)__ldg((const long long*)p + i);
    return __ldg((const int*)p + i);
}

__device__ __forceinline__ unsigned long long pk2(float lo, float hi) {
    unsigned long long r;
    asm("mov.b64 %0, {%1, %2};" : "=l"(r) : "f"(lo), "f"(hi));
    return r;
}
__device__ __forceinline__ void upk2(unsigned long long v, float& lo, float& hi) {
    asm("mov.b64 {%0, %1}, %2;" : "=f"(lo), "=f"(hi) : "l"(v));
}
__device__ __forceinline__ void ffma2(unsigned long long& d, unsigned long long a, unsigned long long b) {
    asm("fma.rn.f32x2 %0, %1, %2, %0;" : "+l"(d) : "l"(a), "l"(b));
}
__device__ __forceinline__ void fadd2(unsigned long long& d, unsigned long long a) {
    asm("add.rn.f32x2 %0, %1, %0;" : "+l"(d) : "l"(a));
}

// ---------------- Kernel 0: fold weights + index dtype detection ----------------
__global__ void k_prep(const float* __restrict__ fc_w,
                       const float* __restrict__ out_proj_w,
                       const float* __restrict__ out_proj_b,
                       const float* __restrict__ fc_b,
                       const int* __restrict__ idx_raw) {
    __shared__ int s_flag;
    int t = threadIdx.x;
    if (t == 0) s_flag = 0;
    __syncthreads();

    if (t < 512) {
        int o = t >> 4, e = t & 15;
        float acc = 0.f;
        #pragma unroll
        for (int j = 0; j < 16; j++) acc += fc_w[o * 16 + j] * out_proj_w[j * 16 + e];
        g_M[o * 16 + e] = acc;
    }
    if (t < 32) {
        float acc = fc_b[t];
        #pragma unroll
        for (int j = 0; j < 16; j++) acc += fc_w[t * 16 + j] * out_proj_b[j];
        g_b32[t] = acc;
    }
    // int64 indices (<2^31) => every odd int32 word of first 128 elements is zero
    if (t < 128 && idx_raw[2 * t + 1] != 0) atomicOr(&s_flag, 1);
    __syncthreads();
    if (t == 0) g_idx64 = (s_flag == 0) ? 1 : 0;
}

// ---------------- Kernel 1: per-node precompute (smem-staged weights) ----------------
__global__ void __launch_bounds__(128)
k_node(const float* __restrict__ nf,
       const float* __restrict__ w1, const float* __restrict__ b1,
       const float* __restrict__ w2, const float* __restrict__ b2,
       const float* __restrict__ wp, const float* __restrict__ bp,
       int N) {
    __shared__ __align__(16) float s_w1[256];   // [32][8] padded rows
    __shared__ __align__(16) float s_w2[512];   // [16][32]
    __shared__ __align__(16) float s_wp[768];   // [48][16]
    __shared__ __align__(16) float s_M[512];    // [32][16]
    __shared__ float s_b1[32], s_b2[16], s_bp[48];

    const int tid = threadIdx.x;

    // stage weights
    #pragma unroll
    for (int i = tid; i < 256; i += 128) {
        int o = i >> 3, c = i & 7;
        s_w1[i] = (c < 6) ? __ldg(w1 + o * 6 + c) : 0.f;
    }
    #pragma unroll
    for (int i = tid; i < 512; i += 128) s_w2[i] = __ldg(w2 + i);
    #pragma unroll
    for (int i = tid; i < 768; i += 128) s_wp[i] = __ldg(wp + i);
    #pragma unroll
    for (int i = tid; i < 512; i += 128) s_M[i] = g_M[i];
    if (tid < 32) s_b1[tid] = __ldg(b1 + tid);
    if (tid < 16) s_b2[tid] = __ldg(b2 + tid);
    if (tid < 48) s_bp[tid] = __ldg(bp + tid);
    __syncthreads();

    int n = blockIdx.x * 128 + tid;
    if (n >= N) return;

    float f[6];
    #pragma unroll
    for (int i = 0; i < 6; i++) f[i] = __ldg(nf + (size_t)n * 6 + i);

    const float4* w1v = (const float4*)s_w1;
    float h[32];
    #pragma unroll
    for (int o = 0; o < 32; o++) {
        float4 a = w1v[o * 2], b = w1v[o * 2 + 1];
        float acc = s_b1[o] + a.x * f[0] + a.y * f[1] + a.z * f[2] + a.w * f[3]
                  + b.x * f[4] + b.y * f[5];
        h[o] = fmaxf(acc, 0.f);
    }

    const float4* w2v = (const float4*)s_w2;
    float x[16];
    #pragma unroll
    for (int e = 0; e < 16; e++) {
        float acc = s_b2[e];
        #pragma unroll
        for (int j = 0; j < 8; j++) {
            float4 w = w2v[e * 8 + j];
            acc += w.x * h[4 * j] + w.y * h[4 * j + 1] + w.z * h[4 * j + 2] + w.w * h[4 * j + 3];
        }
        x[e] = acc;
    }

    const float4* wpv = (const float4*)s_wp;
    float qkv[48];
    #pragma unroll
    for (int o = 0; o < 48; o++) {
        float acc = s_bp[o];
        #pragma unroll
        for (int j = 0; j < 4; j++) {
            float4 w = wpv[o * 4 + j];
            acc += w.x * x[4 * j] + w.y * x[4 * j + 1] + w.z * x[4 * j + 2] + w.w * x[4 * j + 3];
        }
        qkv[o] = acc;
    }

    float4* rec4 = g_pre + (size_t)n * GREC;
    const float s = 0.3535533905932738f;  // 1/sqrt(8) folded into q
    #pragma unroll
    for (int j = 0; j < 4; j++)
        rec4[j] = make_float4(qkv[4 * j] * s, qkv[4 * j + 1] * s, qkv[4 * j + 2] * s, qkv[4 * j + 3] * s);
    #pragma unroll
    for (int j = 0; j < 4; j++)
        rec4[4 + j] = make_float4(qkv[16 + 4 * j], qkv[17 + 4 * j], qkv[18 + 4 * j], qkv[19 + 4 * j]);

    const float4* Mv = (const float4*)s_M;
    #pragma unroll
    for (int h2 = 0; h2 < 2; h2++) {
        float v0 = qkv[32 + h2 * 8 + 0], v1 = qkv[32 + h2 * 8 + 1];
        float v2 = qkv[32 + h2 * 8 + 2], v3 = qkv[32 + h2 * 8 + 3];
        float v4 = qkv[32 + h2 * 8 + 4], v5 = qkv[32 + h2 * 8 + 5];
        float v6 = qkv[32 + h2 * 8 + 6], v7 = qkv[32 + h2 * 8 + 7];
        #pragma unroll
        for (int j = 0; j < 8; j++) {
            float wv[4];
            #pragma unroll
            for (int c = 0; c < 4; c++) {
                int o = 4 * j + c;
                float4 ma = Mv[o * 4 + h2 * 2], mb = Mv[o * 4 + h2 * 2 + 1];
                wv[c] = v0 * ma.x + v1 * ma.y + v2 * ma.z + v3 * ma.w
                      + v4 * mb.x + v5 * mb.y + v6 * mb.z + v7 * mb.w;
            }
            rec4[8 + h2 * 8 + j] = make_float4(wv[0], wv[1], wv[2], wv[3]);
        }
    }
}

// ---------------- Kernel 2: per-loop attention + epilogue ----------------
__global__ void __launch_bounds__(128)
k_loops(const void* __restrict__ s2l,
        const float* __restrict__ fco_w, const float* __restrict__ fco_b,
        float* __restrict__ out, int B) {
    __shared__ __align__(16) float4 s_rec[LPB * 8 * CH];   // 40 KB: k[16] + wfold[64] per slot
    __shared__ __align__(16) float4 s_fcw[256];            // 4 KB, row-swizzled
    __shared__ __align__(16) float  s_b32s[32];
    __shared__ float  s_fcb[32];
    __shared__ int    s_idx[LPB * 8];

    const int tid = threadIdx.x;
    const long long base8 = (long long)blockIdx.x * (LPB * 8);
    const long long total8 = (long long)B * 8;
    const int is64 = g_idx64;

    // ---- phase A: indices + fco weights + biases ----
    {
        long long gi = base8 + tid;
        if (gi >= total8) gi = 0;
        s_idx[tid] = fetch_idx(s2l, gi, is64);
    }
    const float4* fcw4 = (const float4*)fco_w;   // [32 rows][8 float4]
    #pragma unroll
    for (int i = tid; i < 256; i += 128) {
        int r = i >> 3, k4 = i & 7;
        s_fcw[r * 8 + (k4 ^ FKEY(r))] = __ldg(fcw4 + i);
    }
    if (tid < 32) { s_b32s[tid] = g_b32[tid]; s_fcb[tid] = __ldg(fco_b + tid); }
    __syncthreads();

    const int ll = tid >> 3;       // loop within block
    const int l  = tid & 7;        // query row
    const int slot_l = tid;

    // ---- own q from L2 (issued early, consumed after staging) ----
    unsigned long long q2[8];
    {
        const ulonglong2* gq = reinterpret_cast<const ulonglong2*>(g_pre + (size_t)s_idx[slot_l] * GREC);
        ulonglong2 a = __ldg(gq), b = __ldg(gq + 1), c = __ldg(gq + 2), d = __ldg(gq + 3);
        q2[0] = a.x; q2[1] = a.y; q2[2] = b.x; q2[3] = b.y;
        q2[4] = c.x; q2[5] = c.y; q2[6] = d.x; q2[7] = d.y;
    }

    // ---- phase B: stage k + wfold for all 128 slots (swizzled) ----
    #pragma unroll
    for (int it = 0; it < CH; it++) {
        int i = tid + it * 128;          // 0..2559
        int slot = i / CH;
        int c = i - slot * CH;
        int node = s_idx[slot];
        s_rec[slot * CH + (c ^ SKEY(slot))] = __ldg(g_pre + (size_t)node * GREC + 4 + c);
    }
    __syncthreads();

    const ulonglong2* su = reinterpret_cast<const ulonglong2*>(s_rec);

    // ---- scores (both heads), packed dot products ----
    float p0[8], p1[8];
    #pragma unroll
    for (int m = 0; m < 8; m++) {
        int sm = ll * 8 + m;
        int key = SKEY(sm);
        int base = sm * CH;
        ulonglong2 k0 = su[base + (0 ^ key)];
        ulonglong2 k1 = su[base + (1 ^ key)];
        ulonglong2 k2 = su[base + (2 ^ key)];
        ulonglong2 k3 = su[base + (3 ^ key)];
        unsigned long long a0 = 0ULL, a1 = 0ULL;
        ffma2(a0, q2[0], k0.x); ffma2(a0, q2[1], k0.y);
        ffma2(a0, q2[2], k1.x); ffma2(a0, q2[3], k1.y);
        ffma2(a1, q2[4], k2.x); ffma2(a1, q2[5], k2.y);
        ffma2(a1, q2[6], k3.x); ffma2(a1, q2[7], k3.y);
        float lo, hi;
        upk2(a0, lo, hi); p0[m] = lo + hi;
        upk2(a1, lo, hi); p1[m] = lo + hi;
    }

    // ---- softmax over m, per head ----
    {
        float mx0 = p0[0], mx1 = p1[0];
        #pragma unroll
        for (int m = 1; m < 8; m++) { mx0 = fmaxf(mx0, p0[m]); mx1 = fmaxf(mx1, p1[m]); }
        float s0 = 0.f, s1 = 0.f;
        #pragma unroll
        for (int m = 0; m < 8; m++) {
            p0[m] = __expf(p0[m] - mx0); s0 += p0[m];
            p1[m] = __expf(p1[m] - mx1); s1 += p1[m];
        }
        float i0 = __frcp_rn(s0), i1 = __frcp_rn(s1);
        #pragma unroll
        for (int m = 0; m < 8; m++) { p0[m] *= i0; p1[m] *= i1; }
    }

    // ---- z[o] accumulation, packed f32x2 FMAs ----
    unsigned long long z2[16];
    #pragma unroll
    for (int j = 0; j < 16; j++) z2[j] = 0ULL;
    #pragma unroll
    for (int m = 0; m < 8; m++) {
        int sm = ll * 8 + m;
        int key = SKEY(sm);
        int base = sm * CH;
        unsigned long long pp0 = pk2(p0[m], p0[m]);
        unsigned long long pp1 = pk2(p1[m], p1[m]);
        #pragma unroll
        for (int j = 0; j < 8; j++) {
            ulonglong2 wv = su[base + ((4 + j) ^ key)];
            ffma2(z2[2 * j], pp0, wv.x);
            ffma2(z2[2 * j + 1], pp0, wv.y);
        }
        #pragma unroll
        for (int j = 0; j < 8; j++) {
            ulonglong2 wv = su[base + ((12 + j) ^ key)];
            ffma2(z2[2 * j], pp1, wv.x);
            ffma2(z2[2 * j + 1], pp1, wv.y);
        }
    }

    // ---- t = relu(z + bias32); butterfly-sum over 8 query rows; mean ----
    float t[32];
    {
        const unsigned long long* b2p = reinterpret_cast<const unsigned long long*>(s_b32s);
        #pragma unroll
        for (int j = 0; j < 16; j++) {
            fadd2(z2[j], b2p[j]);
            float lo, hi;
            upk2(z2[j], lo, hi);
            t[2 * j] = fmaxf(lo, 0.f);
            t[2 * j + 1] = fmaxf(hi, 0.f);
        }
    }
    #pragma unroll
    for (int st = 0; st < 3; st++) {
        int mask = 1 << st;  // stays within each 8-lane loop group
        #pragma unroll
        for (int o = 0; o < 32; o++) t[o] += __shfl_xor_sync(0xffffffffu, t[o], mask);
    }
    unsigned long long t2[16];
    #pragma unroll
    for (int j = 0; j < 16; j++) t2[j] = pk2(t[2 * j] * 0.125f, t[2 * j + 1] * 0.125f);

    // ---- fco: each of 8 lanes computes 4 outputs (packed, swizzled smem) ----
    const ulonglong2* sf = reinterpret_cast<const ulonglong2*>(s_fcw);
    float r[4];
    #pragma unroll
    for (int jj = 0; jj < 4; jj++) {
        int o2 = l * 4 + jj;
        int key = FKEY(o2);
        unsigned long long acc = 0ULL;
        #pragma unroll
        for (int k4 = 0; k4 < 8; k4++) {
            ulonglong2 wv = sf[o2 * 8 + (k4 ^ key)];
            ffma2(acc, t2[2 * k4], wv.x);
            ffma2(acc, t2[2 * k4 + 1], wv.y);
        }
        float lo, hi;
        upk2(acc, lo, hi);
        r[jj] = lo + hi + s_fcb[o2];
    }

    long long lg = (long long)blockIdx.x * LPB + ll;
    if (lg < B)
        reinterpret_cast<float4*>(out)[lg * 8 + l] = make_float4(r[0], r[1], r[2], r[3]);
}

// ---------------- launch ----------------
extern "C" void kernel_launch(void* const* d_in, const int* in_sizes, int n_in,
                              void* d_out, int out_size) {
    const float* node_features = (const float*)d_in[0];
    const void*  stroke_to_loop = d_in[1];
    const float* fc1_w = (const float*)d_in[2];
    const float* fc1_b = (const float*)d_in[3];
    const float* fc2_w = (const float*)d_in[4];
    const float* fc2_b = (const float*)d_in[5];
    const float* in_proj_w = (const float*)d_in[6];
    const float* in_proj_b = (const float*)d_in[7];
    const float* out_proj_w = (const float*)d_in[8];
    const float* out_proj_b = (const float*)d_in[9];
    const float* fc_w = (const float*)d_in[10];
    const float* fc_b = (const float*)d_in[11];
    const float* fco_w = (const float*)d_in[12];
    const float* fco_b = (const float*)d_in[13];

    int N = in_sizes[0] / 6;
    int B = in_sizes[1] / 8;

    k_prep<<<1, 512>>>(fc_w, out_proj_w, out_proj_b, fc_b, (const int*)stroke_to_loop);
    k_node<<<(N + 127) / 128, 128>>>(node_features, fc1_w, fc1_b, fc2_w, fc2_b,
                                     in_proj_w, in_proj_b, N);
    k_loops<<<(B + LPB - 1) / LPB, 128>>>(stroke_to_loop, fco_w, fco_b, (float*)d_out, B);
}

// round 3
// speedup vs baseline: 2.1993x; 1.4398x over previous
#include <cuda_runtime.h>
#include <cstdint>

#define NMAX 100000
#define GREC 12            // float4 chunks per node record (48 floats: q,k,v)
#define LPB  16            // loops per block in k_loops

// Scratch (static __device__ — no runtime allocation)
__device__ float4 g_pre[(size_t)NMAX * GREC];   // per-node: q*invsqrt8[16], k[16], v[16]
__device__ float  g_Mt[16 * 32];                // (fc_w @ out_proj_w)^T : [e][o]
__device__ float  g_b32[32];                    // fc_w @ out_proj_b + fc_b
__device__ int    g_idx64;                      // 1 if stroke_to_loop is int64

// chunk swizzle inside a slot: key distinct across the 4 loop-groups of a warp
#define SKEY(slot) (((slot) ^ ((slot) >> 3)) & 3)
// fco row swizzle: key injective over the 8 lanes of a loop group
#define FKEY(o) ((((o) ^ ((o) >> 2))) & 7)

__device__ __forceinline__ int fetch_idx(const void* p, long long i, int is64) {
    if (is64) return (int)__ldg((const long long*)p + i);
    return __ldg((const int*)p + i);
}
__device__ __forceinline__ unsigned long long pk2(float lo, float hi) {
    unsigned long long r;
    asm("mov.b64 %0, {%1, %2};" : "=l"(r) : "f"(lo), "f"(hi));
    return r;
}
__device__ __forceinline__ void upk2(unsigned long long v, float& lo, float& hi) {
    asm("mov.b64 {%0, %1}, %2;" : "=f"(lo), "=f"(hi) : "l"(v));
}
__device__ __forceinline__ void ffma2(unsigned long long& d, unsigned long long a, unsigned long long b) {
    asm("fma.rn.f32x2 %0, %1, %2, %0;" : "+l"(d) : "l"(a), "l"(b));
}
__device__ __forceinline__ void fadd2(unsigned long long& d, unsigned long long a) {
    asm("add.rn.f32x2 %0, %1, %0;" : "+l"(d) : "l"(a));
}
__device__ __forceinline__ void cpa16(uint32_t dst_smem, const void* src) {
    asm volatile("cp.async.cg.shared.global [%0], [%1], 16;" :: "r"(dst_smem), "l"(src));
}

// ---------------- Kernel 1: per-node precompute (+ fused prep in block 0) ----------------
__global__ void __launch_bounds__(128)
k_node(const float* __restrict__ nf,
       const float* __restrict__ w1, const float* __restrict__ b1,
       const float* __restrict__ w2, const float* __restrict__ b2,
       const float* __restrict__ wp, const float* __restrict__ bp,
       const float* __restrict__ fc_w, const float* __restrict__ opw,
       const float* __restrict__ opb, const float* __restrict__ fc_b,
       const int* __restrict__ idx_raw, int N) {
    __shared__ __align__(16) float s_w1[256];   // [32][8] padded rows
    __shared__ __align__(16) float s_w2[512];   // [16][32]
    __shared__ __align__(16) float s_wp[768];   // [48][16]
    __shared__ float s_b1[32], s_b2[16], s_bp[48];
    __shared__ int s_flag;

    const int tid = threadIdx.x;

    // ---- block 0 extra: fold weights + index dtype detection ----
    if (blockIdx.x == 0) {
        if (tid == 0) s_flag = 0;
        #pragma unroll
        for (int i = tid; i < 512; i += 128) {
            int o = i >> 4, e = i & 15;
            float acc = 0.f;
            #pragma unroll
            for (int j = 0; j < 16; j++) acc += __ldg(fc_w + o * 16 + j) * __ldg(opw + j * 16 + e);
            g_Mt[e * 32 + o] = acc;
        }
        if (tid < 32) {
            float acc = __ldg(fc_b + tid);
            #pragma unroll
            for (int j = 0; j < 16; j++) acc += __ldg(fc_w + tid * 16 + j) * __ldg(opb + j);
            g_b32[tid] = acc;
        }
        __syncthreads();
        // int64 indices (<2^31) => odd int32 words of first 128 elements are zero
        if (tid < 128 && __ldg(idx_raw + 2 * tid + 1) != 0) atomicOr(&s_flag, 1);
        __syncthreads();
        if (tid == 0) g_idx64 = (s_flag == 0) ? 1 : 0;
    }

    // ---- stage weights ----
    #pragma unroll
    for (int i = tid; i < 256; i += 128) {
        int o = i >> 3, c = i & 7;
        s_w1[i] = (c < 6) ? __ldg(w1 + o * 6 + c) : 0.f;
    }
    #pragma unroll
    for (int i = tid; i < 512; i += 128) s_w2[i] = __ldg(w2 + i);
    #pragma unroll
    for (int i = tid; i < 768; i += 128) s_wp[i] = __ldg(wp + i);
    if (tid < 32) s_b1[tid] = __ldg(b1 + tid);
    if (tid < 16) s_b2[tid] = __ldg(b2 + tid);
    if (tid < 48) s_bp[tid] = __ldg(bp + tid);
    __syncthreads();

    int n = blockIdx.x * 128 + tid;
    if (n >= N) return;

    float f[6];
    #pragma unroll
    for (int i = 0; i < 6; i++) f[i] = __ldg(nf + (size_t)n * 6 + i);

    const float4* w1v = (const float4*)s_w1;
    float h[32];
    #pragma unroll
    for (int o = 0; o < 32; o++) {
        float4 a = w1v[o * 2], b = w1v[o * 2 + 1];
        float acc = s_b1[o] + a.x * f[0] + a.y * f[1] + a.z * f[2] + a.w * f[3]
                  + b.x * f[4] + b.y * f[5];
        h[o] = fmaxf(acc, 0.f);
    }
    const float4* w2v = (const float4*)s_w2;
    float x[16];
    #pragma unroll
    for (int e = 0; e < 16; e++) {
        float acc = s_b2[e];
        #pragma unroll
        for (int j = 0; j < 8; j++) {
            float4 w = w2v[e * 8 + j];
            acc += w.x * h[4 * j] + w.y * h[4 * j + 1] + w.z * h[4 * j + 2] + w.w * h[4 * j + 3];
        }
        x[e] = acc;
    }
    const float4* wpv = (const float4*)s_wp;
    float qkv[48];
    #pragma unroll
    for (int o = 0; o < 48; o++) {
        float acc = s_bp[o];
        #pragma unroll
        for (int j = 0; j < 4; j++) {
            float4 w = wpv[o * 4 + j];
            acc += w.x * x[4 * j] + w.y * x[4 * j + 1] + w.z * x[4 * j + 2] + w.w * x[4 * j + 3];
        }
        qkv[o] = acc;
    }

    float4* rec4 = g_pre + (size_t)n * GREC;
    const float s = 0.3535533905932738f;  // 1/sqrt(8) folded into q
    #pragma unroll
    for (int j = 0; j < 4; j++)
        rec4[j] = make_float4(qkv[4 * j] * s, qkv[4 * j + 1] * s, qkv[4 * j + 2] * s, qkv[4 * j + 3] * s);
    #pragma unroll
    for (int j = 0; j < 8; j++)
        rec4[4 + j] = make_float4(qkv[16 + 4 * j], qkv[17 + 4 * j], qkv[18 + 4 * j], qkv[19 + 4 * j]);
}

// ---------------- Kernel 2: per-loop attention + epilogue ----------------
__global__ void __launch_bounds__(128)
k_loops(const void* __restrict__ s2l,
        const float* __restrict__ fco_w, const float* __restrict__ fco_b,
        float* __restrict__ out, int B) {
    __shared__ __align__(16) float4 s_rec[LPB * 8 * 8];    // 16 KB: k[16]+v[16] per slot, swizzled
    __shared__ __align__(16) float4 s_fcw[256];            // 4 KB, row-swizzled
    __shared__ __align__(16) float4 s_Mt[128];             // 2 KB: Mt[e][o], broadcast reads
    __shared__ __align__(16) float  s_b32s[32];
    __shared__ float  s_fcb[32];
    __shared__ int    s_idx[LPB * 8];

    const int tid = threadIdx.x;
    const long long base8 = (long long)blockIdx.x * (LPB * 8);
    const long long total8 = (long long)B * 8;
    const int is64 = g_idx64;

    // ---- phase A: indices + shared weights ----
    int node_own;
    {
        long long gi = base8 + tid;
        if (gi >= total8) gi = 0;
        node_own = fetch_idx(s2l, gi, is64);
        s_idx[tid] = node_own;
    }
    const float4* fcw4 = (const float4*)fco_w;   // [32 rows][8 float4]
    #pragma unroll
    for (int i = tid; i < 256; i += 128) {
        int r = i >> 3, k4 = i & 7;
        s_fcw[r * 8 + (k4 ^ FKEY(r))] = __ldg(fcw4 + i);
    }
    s_Mt[tid] = __ldg((const float4*)g_Mt + tid);
    if (tid < 32) { s_b32s[tid] = g_b32[tid]; s_fcb[tid] = __ldg(fco_b + tid); }

    // ---- own q from L2 (own index known without sync) ----
    unsigned long long q2[8];
    {
        const ulonglong2* gq = reinterpret_cast<const ulonglong2*>(g_pre + (size_t)node_own * GREC);
        ulonglong2 a = __ldg(gq), b = __ldg(gq + 1), c = __ldg(gq + 2), d = __ldg(gq + 3);
        q2[0] = a.x; q2[1] = a.y; q2[2] = b.x; q2[3] = b.y;
        q2[4] = c.x; q2[5] = c.y; q2[6] = d.x; q2[7] = d.y;
    }
    __syncthreads();   // s_idx visible to all

    // ---- phase B: cp.async stage k+v for all 128 slots (swizzled) ----
    {
        const int c = tid & 7, sb = tid >> 3;
        #pragma unroll
        for (int it = 0; it < 8; it++) {
            int slot = it * 16 + sb;
            int node = s_idx[slot];
            uint32_t dst = (uint32_t)__cvta_generic_to_shared(&s_rec[slot * 8 + (c ^ SKEY(slot))]);
            cpa16(dst, g_pre + (size_t)node * GREC + 4 + c);
        }
        asm volatile("cp.async.commit_group;");
        asm volatile("cp.async.wait_group 0;");
    }
    __syncthreads();

    const ulonglong2* su = reinterpret_cast<const ulonglong2*>(s_rec);
    const int ll = tid >> 3;       // loop within block
    const int l  = tid & 7;        // query row

    // ---- scores (both heads), packed dot products ----
    float p0[8], p1[8];
    #pragma unroll
    for (int m = 0; m < 8; m++) {
        int sm = ll * 8 + m;
        int key = SKEY(sm);
        int base = sm * 8;
        ulonglong2 k0 = su[base + (0 ^ key)];
        ulonglong2 k1 = su[base + (1 ^ key)];
        ulonglong2 k2 = su[base + (2 ^ key)];
        ulonglong2 k3 = su[base + (3 ^ key)];
        unsigned long long a0 = 0ULL, a1 = 0ULL;
        ffma2(a0, q2[0], k0.x); ffma2(a0, q2[1], k0.y);
        ffma2(a0, q2[2], k1.x); ffma2(a0, q2[3], k1.y);
        ffma2(a1, q2[4], k2.x); ffma2(a1, q2[5], k2.y);
        ffma2(a1, q2[6], k3.x); ffma2(a1, q2[7], k3.y);
        float lo, hi;
        upk2(a0, lo, hi); p0[m] = lo + hi;
        upk2(a1, lo, hi); p1[m] = lo + hi;
    }

    // ---- softmax over m, per head ----
    {
        float mx0 = p0[0], mx1 = p1[0];
        #pragma unroll
        for (int m = 1; m < 8; m++) { mx0 = fmaxf(mx0, p0[m]); mx1 = fmaxf(mx1, p1[m]); }
        float s0 = 0.f, s1 = 0.f;
        #pragma unroll
        for (int m = 0; m < 8; m++) {
            p0[m] = __expf(p0[m] - mx0); s0 += p0[m];
            p1[m] = __expf(p1[m] - mx1); s1 += p1[m];
        }
        float i0 = __frcp_rn(s0), i1 = __frcp_rn(s1);
        #pragma unroll
        for (int m = 0; m < 8; m++) { p0[m] *= i0; p1[m] *= i1; }
    }

    // ---- ctx[16] = sum_m p * v, packed ----
    unsigned long long cx2[8];
    #pragma unroll
    for (int j = 0; j < 8; j++) cx2[j] = 0ULL;
    #pragma unroll
    for (int m = 0; m < 8; m++) {
        int sm = ll * 8 + m;
        int key = SKEY(sm);
        int base = sm * 8;
        unsigned long long pp0 = pk2(p0[m], p0[m]);
        unsigned long long pp1 = pk2(p1[m], p1[m]);
        ulonglong2 v0 = su[base + (4 ^ key)];
        ulonglong2 v1 = su[base + (5 ^ key)];
        ulonglong2 v2 = su[base + (6 ^ key)];
        ulonglong2 v3 = su[base + (7 ^ key)];
        ffma2(cx2[0], pp0, v0.x); ffma2(cx2[1], pp0, v0.y);
        ffma2(cx2[2], pp0, v1.x); ffma2(cx2[3], pp0, v1.y);
        ffma2(cx2[4], pp1, v2.x); ffma2(cx2[5], pp1, v2.y);
        ffma2(cx2[6], pp1, v3.x); ffma2(cx2[7], pp1, v3.y);
    }
    float ce[16];
    #pragma unroll
    for (int j = 0; j < 8; j++) upk2(cx2[j], ce[2 * j], ce[2 * j + 1]);

    // ---- z[32] = Mt^T ctx via broadcast smem reads of Mt rows ----
    unsigned long long z2[16];
    #pragma unroll
    for (int j = 0; j < 16; j++) z2[j] = 0ULL;
    const ulonglong2* suM = reinterpret_cast<const ulonglong2*>(s_Mt);
    #pragma unroll
    for (int e = 0; e < 16; e++) {
        unsigned long long pce = pk2(ce[e], ce[e]);
        #pragma unroll
        for (int j4 = 0; j4 < 8; j4++) {
            ulonglong2 wv = suM[e * 8 + j4];
            ffma2(z2[2 * j4], pce, wv.x);
            ffma2(z2[2 * j4 + 1], pce, wv.y);
        }
    }

    // ---- t = relu(z + bias32); butterfly-sum over 8 query rows; mean ----
    float t[32];
    {
        const unsigned long long* b2p = reinterpret_cast<const unsigned long long*>(s_b32s);
        #pragma unroll
        for (int j = 0; j < 16; j++) {
            fadd2(z2[j], b2p[j]);
            float lo, hi;
            upk2(z2[j], lo, hi);
            t[2 * j] = fmaxf(lo, 0.f);
            t[2 * j + 1] = fmaxf(hi, 0.f);
        }
    }
    #pragma unroll
    for (int st = 0; st < 3; st++) {
        int mask = 1 << st;  // stays within each 8-lane loop group
        #pragma unroll
        for (int o = 0; o < 32; o++) t[o] += __shfl_xor_sync(0xffffffffu, t[o], mask);
    }
    unsigned long long t2[16];
    #pragma unroll
    for (int j = 0; j < 16; j++) t2[j] = pk2(t[2 * j] * 0.125f, t[2 * j + 1] * 0.125f);

    // ---- fco: each of 8 lanes computes 4 outputs (packed, swizzled smem) ----
    const ulonglong2* sf = reinterpret_cast<const ulonglong2*>(s_fcw);
    float r[4];
    #pragma unroll
    for (int jj = 0; jj < 4; jj++) {
        int o2 = l * 4 + jj;
        int key = FKEY(o2);
        unsigned long long acc = 0ULL;
        #pragma unroll
        for (int k4 = 0; k4 < 8; k4++) {
            ulonglong2 wv = sf[o2 * 8 + (k4 ^ key)];
            ffma2(acc, t2[2 * k4], wv.x);
            ffma2(acc, t2[2 * k4 + 1], wv.y);
        }
        float lo, hi;
        upk2(acc, lo, hi);
        r[jj] = lo + hi + s_fcb[o2];
    }

    long long lg = (long long)blockIdx.x * LPB + ll;
    if (lg < B)
        reinterpret_cast<float4*>(out)[lg * 8 + l] = make_float4(r[0], r[1], r[2], r[3]);
}

// ---------------- launch ----------------
extern "C" void kernel_launch(void* const* d_in, const int* in_sizes, int n_in,
                              void* d_out, int out_size) {
    const float* node_features = (const float*)d_in[0];
    const void*  stroke_to_loop = d_in[1];
    const float* fc1_w = (const float*)d_in[2];
    const float* fc1_b = (const float*)d_in[3];
    const float* fc2_w = (const float*)d_in[4];
    const float* fc2_b = (const float*)d_in[5];
    const float* in_proj_w = (const float*)d_in[6];
    const float* in_proj_b = (const float*)d_in[7];
    const float* out_proj_w = (const float*)d_in[8];
    const float* out_proj_b = (const float*)d_in[9];
    const float* fc_w = (const float*)d_in[10];
    const float* fc_b = (const float*)d_in[11];
    const float* fco_w = (const float*)d_in[12];
    const float* fco_b = (const float*)d_in[13];

    int N = in_sizes[0] / 6;
    int B = in_sizes[1] / 8;

    k_node<<<(N + 127) / 128, 128>>>(node_features, fc1_w, fc1_b, fc2_w, fc2_b,
                                     in_proj_w, in_proj_b,
                                     fc_w, out_proj_w, out_proj_b, fc_b,
                                     (const int*)stroke_to_loop, N);
    k_loops<<<(B + LPB - 1) / LPB, 128>>>(stroke_to_loop, fco_w, fco_b, (float*)d_out, B);
}

// round 4
// speedup vs baseline: 2.9320x; 1.3332x over previous
#include <cuda_runtime.h>
#include <cstdint>

#define NMAX 100000
#define GREC 12            // float4 chunks per node record (48 floats: q,k,v)
#define LPB  32            // loops per block in k_loops (4 threads per loop)

// Scratch (static __device__ — no runtime allocation)
__device__ float4 g_pre[(size_t)NMAX * GREC];   // per-node: q*invsqrt8[16], k[16], v[16]
__device__ float  g_Mt[16 * 32];                // (fc_w @ out_proj_w)^T : [e][o]
__device__ float  g_b32[32];                    // fc_w @ out_proj_b + fc_b
__device__ int    g_idx64;                      // 1 if stroke_to_loop is int64

// chunk swizzle inside a slot: key distinct across the 8 loop-groups of a warp
#define SKEY(slot) (((slot) ^ ((slot) >> 3)) & 7)
// fco row swizzle: key distinct over the 4 lanes of a loop group
#define FKEY(o) (((o) >> 3) & 3)

__device__ __forceinline__ int fetch_idx(const void* p, long long i, int is64) {
    if (is64) return (int)__ldg((const long long*)p + i);
    return __ldg((const int*)p + i);
}
__device__ __forceinline__ unsigned long long pk2(float lo, float hi) {
    unsigned long long r;
    asm("mov.b64 %0, {%1, %2};" : "=l"(r) : "f"(lo), "f"(hi));
    return r;
}
__device__ __forceinline__ void upk2(unsigned long long v, float& lo, float& hi) {
    asm("mov.b64 {%0, %1}, %2;" : "=f"(lo), "=f"(hi) : "l"(v));
}
__device__ __forceinline__ void ffma2(unsigned long long& d, unsigned long long a, unsigned long long b) {
    asm("fma.rn.f32x2 %0, %1, %2, %0;" : "+l"(d) : "l"(a), "l"(b));
}
__device__ __forceinline__ void fadd2(unsigned long long& d, unsigned long long a) {
    asm("add.rn.f32x2 %0, %1, %0;" : "+l"(d) : "l"(a));
}
__device__ __forceinline__ void cpa16(uint32_t dst_smem, const void* src) {
    asm volatile("cp.async.cg.shared.global [%0], [%1], 16;" :: "r"(dst_smem), "l"(src));
}

// ---------------- Kernel 1: per-node precompute (+ fused prep in block 0) ----------------
__global__ void __launch_bounds__(128)
k_node(const float* __restrict__ nf,
       const float* __restrict__ w1, const float* __restrict__ b1,
       const float* __restrict__ w2, const float* __restrict__ b2,
       const float* __restrict__ wp, const float* __restrict__ bp,
       const float* __restrict__ fc_w, const float* __restrict__ opw,
       const float* __restrict__ opb, const float* __restrict__ fc_b,
       const int* __restrict__ idx_raw, int N) {
    __shared__ __align__(16) float s_w1[256];   // [32][8] padded rows
    __shared__ __align__(16) float s_w2[512];   // [16][32]
    __shared__ __align__(16) float s_wp[768];   // [48][16]
    __shared__ float s_b1[32], s_b2[16], s_bp[48];
    __shared__ int s_flag;

    const int tid = threadIdx.x;

    if (blockIdx.x == 0) {
        if (tid == 0) s_flag = 0;
        #pragma unroll
        for (int i = tid; i < 512; i += 128) {
            int o = i >> 4, e = i & 15;
            float acc = 0.f;
            #pragma unroll
            for (int j = 0; j < 16; j++) acc += __ldg(fc_w + o * 16 + j) * __ldg(opw + j * 16 + e);
            g_Mt[e * 32 + o] = acc;
        }
        if (tid < 32) {
            float acc = __ldg(fc_b + tid);
            #pragma unroll
            for (int j = 0; j < 16; j++) acc += __ldg(fc_w + tid * 16 + j) * __ldg(opb + j);
            g_b32[tid] = acc;
        }
        __syncthreads();
        if (tid < 128 && __ldg(idx_raw + 2 * tid + 1) != 0) atomicOr(&s_flag, 1);
        __syncthreads();
        if (tid == 0) g_idx64 = (s_flag == 0) ? 1 : 0;
    }

    #pragma unroll
    for (int i = tid; i < 256; i += 128) {
        int o = i >> 3, c = i & 7;
        s_w1[i] = (c < 6) ? __ldg(w1 + o * 6 + c) : 0.f;
    }
    #pragma unroll
    for (int i = tid; i < 512; i += 128) s_w2[i] = __ldg(w2 + i);
    #pragma unroll
    for (int i = tid; i < 768; i += 128) s_wp[i] = __ldg(wp + i);
    if (tid < 32) s_b1[tid] = __ldg(b1 + tid);
    if (tid < 16) s_b2[tid] = __ldg(b2 + tid);
    if (tid < 48) s_bp[tid] = __ldg(bp + tid);
    __syncthreads();

    int n = blockIdx.x * 128 + tid;
    if (n >= N) return;

    float f[6];
    #pragma unroll
    for (int i = 0; i < 6; i++) f[i] = __ldg(nf + (size_t)n * 6 + i);

    const float4* w1v = (const float4*)s_w1;
    float h[32];
    #pragma unroll
    for (int o = 0; o < 32; o++) {
        float4 a = w1v[o * 2], b = w1v[o * 2 + 1];
        float acc = s_b1[o] + a.x * f[0] + a.y * f[1] + a.z * f[2] + a.w * f[3]
                  + b.x * f[4] + b.y * f[5];
        h[o] = fmaxf(acc, 0.f);
    }
    const float4* w2v = (const float4*)s_w2;
    float x[16];
    #pragma unroll
    for (int e = 0; e < 16; e++) {
        float acc = s_b2[e];
        #pragma unroll
        for (int j = 0; j < 8; j++) {
            float4 w = w2v[e * 8 + j];
            acc += w.x * h[4 * j] + w.y * h[4 * j + 1] + w.z * h[4 * j + 2] + w.w * h[4 * j + 3];
        }
        x[e] = acc;
    }
    const float4* wpv = (const float4*)s_wp;
    float qkv[48];
    #pragma unroll
    for (int o = 0; o < 48; o++) {
        float acc = s_bp[o];
        #pragma unroll
        for (int j = 0; j < 4; j++) {
            float4 w = wpv[o * 4 + j];
            acc += w.x * x[4 * j] + w.y * x[4 * j + 1] + w.z * x[4 * j + 2] + w.w * x[4 * j + 3];
        }
        qkv[o] = acc;
    }

    float4* rec4 = g_pre + (size_t)n * GREC;
    const float s = 0.3535533905932738f;  // 1/sqrt(8) folded into q
    #pragma unroll
    for (int j = 0; j < 4; j++)
        rec4[j] = make_float4(qkv[4 * j] * s, qkv[4 * j + 1] * s, qkv[4 * j + 2] * s, qkv[4 * j + 3] * s);
    #pragma unroll
    for (int j = 0; j < 8; j++)
        rec4[4 + j] = make_float4(qkv[16 + 4 * j], qkv[17 + 4 * j], qkv[18 + 4 * j], qkv[19 + 4 * j]);
}

// ---------------- Kernel 2: per-loop attention + epilogue ----------------
// 32 loops/block, 4 threads/loop, each thread handles query rows {j, j+4}.
__global__ void __launch_bounds__(128)
k_loops(const void* __restrict__ s2l,
        const float* __restrict__ fco_w, const float* __restrict__ fco_b,
        float* __restrict__ out, int B) {
    __shared__ __align__(16) float4 s_rec[LPB * 8 * 8];    // 32 KB: k[16]+v[16] per slot, swizzled
    __shared__ __align__(16) float4 s_fcw[256];            // 4 KB, row-swizzled
    __shared__ __align__(16) float4 s_Mt[128];             // 2 KB: Mt[e][o], broadcast reads
    __shared__ __align__(16) float  s_b32s[32];
    __shared__ float  s_fcb[32];
    __shared__ int    s_idx[LPB * 8];

    const int tid = threadIdx.x;
    const long long base8 = (long long)blockIdx.x * (LPB * 8);
    const long long total8 = (long long)B * 8;
    const int is64 = g_idx64;

    // ---- phase A: indices + shared weights ----
    #pragma unroll
    for (int i = 0; i < 2; i++) {
        long long gi = base8 + tid + i * 128;
        if (gi >= total8) gi = 0;
        s_idx[tid + i * 128] = fetch_idx(s2l, gi, is64);
    }
    const float4* fcw4 = (const float4*)fco_w;   // [32 rows][8 float4]
    #pragma unroll
    for (int i = tid; i < 256; i += 128) {
        int r = i >> 3, k4 = i & 7;
        s_fcw[r * 8 + (k4 ^ FKEY(r))] = __ldg(fcw4 + i);
    }
    s_Mt[tid] = __ldg((const float4*)g_Mt + tid);
    if (tid < 32) { s_b32s[tid] = g_b32[tid]; s_fcb[tid] = __ldg(fco_b + tid); }
    __syncthreads();

    const int ll = tid >> 2;       // loop within block (0..31)
    const int lj = tid & 3;        // lane within loop; query rows lj and lj+4
    const int slotA = ll * 8 + lj;
    const int slotB = slotA + 4;

    // ---- own q rows from L2 ----
    unsigned long long q2A[8], q2B[8];
    {
        const ulonglong2* gq = reinterpret_cast<const ulonglong2*>(g_pre + (size_t)s_idx[slotA] * GREC);
        ulonglong2 a = __ldg(gq), b = __ldg(gq + 1), c = __ldg(gq + 2), d = __ldg(gq + 3);
        q2A[0] = a.x; q2A[1] = a.y; q2A[2] = b.x; q2A[3] = b.y;
        q2A[4] = c.x; q2A[5] = c.y; q2A[6] = d.x; q2A[7] = d.y;
    }
    {
        const ulonglong2* gq = reinterpret_cast<const ulonglong2*>(g_pre + (size_t)s_idx[slotB] * GREC);
        ulonglong2 a = __ldg(gq), b = __ldg(gq + 1), c = __ldg(gq + 2), d = __ldg(gq + 3);
        q2B[0] = a.x; q2B[1] = a.y; q2B[2] = b.x; q2B[3] = b.y;
        q2B[4] = c.x; q2B[5] = c.y; q2B[6] = d.x; q2B[7] = d.y;
    }

    // ---- phase B: cp.async stage k+v for all 256 slots (swizzled) ----
    {
        const int c = tid & 7, sb = tid >> 3;   // 16 slot-groups
        #pragma unroll
        for (int it = 0; it < 16; it++) {
            int slot = it * 16 + sb;
            int node = s_idx[slot];
            uint32_t dst = (uint32_t)__cvta_generic_to_shared(&s_rec[slot * 8 + (c ^ SKEY(slot))]);
            cpa16(dst, g_pre + (size_t)node * GREC + 4 + c);
        }
        asm volatile("cp.async.commit_group;");
        asm volatile("cp.async.wait_group 0;");
    }
    __syncthreads();

    const ulonglong2* su = reinterpret_cast<const ulonglong2*>(s_rec);

    // ---- scores (both heads, both rows); k tiles shared across the 2 rows ----
    float p0A[8], p1A[8], p0B[8], p1B[8];
    #pragma unroll
    for (int m = 0; m < 8; m++) {
        int sm = ll * 8 + m;
        int key = SKEY(sm);
        int base = sm * 8;
        ulonglong2 k0 = su[base + (0 ^ key)];
        ulonglong2 k1 = su[base + (1 ^ key)];
        ulonglong2 k2 = su[base + (2 ^ key)];
        ulonglong2 k3 = su[base + (3 ^ key)];
        unsigned long long a0 = 0ULL, a1 = 0ULL, b0 = 0ULL, b1 = 0ULL;
        ffma2(a0, q2A[0], k0.x); ffma2(a0, q2A[1], k0.y);
        ffma2(a0, q2A[2], k1.x); ffma2(a0, q2A[3], k1.y);
        ffma2(a1, q2A[4], k2.x); ffma2(a1, q2A[5], k2.y);
        ffma2(a1, q2A[6], k3.x); ffma2(a1, q2A[7], k3.y);
        ffma2(b0, q2B[0], k0.x); ffma2(b0, q2B[1], k0.y);
        ffma2(b0, q2B[2], k1.x); ffma2(b0, q2B[3], k1.y);
        ffma2(b1, q2B[4], k2.x); ffma2(b1, q2B[5], k2.y);
        ffma2(b1, q2B[6], k3.x); ffma2(b1, q2B[7], k3.y);
        float lo, hi;
        upk2(a0, lo, hi); p0A[m] = lo + hi;
        upk2(a1, lo, hi); p1A[m] = lo + hi;
        upk2(b0, lo, hi); p0B[m] = lo + hi;
        upk2(b1, lo, hi); p1B[m] = lo + hi;
    }

    // ---- softmax over m, per head, per row ----
    {
        float mx0 = p0A[0], mx1 = p1A[0], mx2 = p0B[0], mx3 = p1B[0];
        #pragma unroll
        for (int m = 1; m < 8; m++) {
            mx0 = fmaxf(mx0, p0A[m]); mx1 = fmaxf(mx1, p1A[m]);
            mx2 = fmaxf(mx2, p0B[m]); mx3 = fmaxf(mx3, p1B[m]);
        }
        float s0 = 0.f, s1 = 0.f, s2 = 0.f, s3 = 0.f;
        #pragma unroll
        for (int m = 0; m < 8; m++) {
            p0A[m] = __expf(p0A[m] - mx0); s0 += p0A[m];
            p1A[m] = __expf(p1A[m] - mx1); s1 += p1A[m];
            p0B[m] = __expf(p0B[m] - mx2); s2 += p0B[m];
            p1B[m] = __expf(p1B[m] - mx3); s3 += p1B[m];
        }
        float i0 = __frcp_rn(s0), i1 = __frcp_rn(s1), i2 = __frcp_rn(s2), i3 = __frcp_rn(s3);
        #pragma unroll
        for (int m = 0; m < 8; m++) {
            p0A[m] *= i0; p1A[m] *= i1; p0B[m] *= i2; p1B[m] *= i3;
        }
    }

    // ---- ctx for both rows; v tiles shared ----
    unsigned long long cxA[8], cxB[8];
    #pragma unroll
    for (int j = 0; j < 8; j++) { cxA[j] = 0ULL; cxB[j] = 0ULL; }
    #pragma unroll
    for (int m = 0; m < 8; m++) {
        int sm = ll * 8 + m;
        int key = SKEY(sm);
        int base = sm * 8;
        ulonglong2 v0 = su[base + (4 ^ key)];
        ulonglong2 v1 = su[base + (5 ^ key)];
        ulonglong2 v2 = su[base + (6 ^ key)];
        ulonglong2 v3 = su[base + (7 ^ key)];
        unsigned long long ppA0 = pk2(p0A[m], p0A[m]);
        unsigned long long ppA1 = pk2(p1A[m], p1A[m]);
        unsigned long long ppB0 = pk2(p0B[m], p0B[m]);
        unsigned long long ppB1 = pk2(p1B[m], p1B[m]);
        ffma2(cxA[0], ppA0, v0.x); ffma2(cxA[1], ppA0, v0.y);
        ffma2(cxA[2], ppA0, v1.x); ffma2(cxA[3], ppA0, v1.y);
        ffma2(cxA[4], ppA1, v2.x); ffma2(cxA[5], ppA1, v2.y);
        ffma2(cxA[6], ppA1, v3.x); ffma2(cxA[7], ppA1, v3.y);
        ffma2(cxB[0], ppB0, v0.x); ffma2(cxB[1], ppB0, v0.y);
        ffma2(cxB[2], ppB0, v1.x); ffma2(cxB[3], ppB0, v1.y);
        ffma2(cxB[4], ppB1, v2.x); ffma2(cxB[5], ppB1, v2.y);
        ffma2(cxB[6], ppB1, v3.x); ffma2(cxB[7], ppB1, v3.y);
    }
    float ceA[16], ceB[16];
    #pragma unroll
    for (int j = 0; j < 8; j++) {
        upk2(cxA[j], ceA[2 * j], ceA[2 * j + 1]);
        upk2(cxB[j], ceB[2 * j], ceB[2 * j + 1]);
    }

    // ---- z = Mt^T ctx for both rows, two o-passes; relu+bias+local row-sum ----
    const ulonglong2* suM = reinterpret_cast<const ulonglong2*>(s_Mt);
    const unsigned long long* b2p = reinterpret_cast<const unsigned long long*>(s_b32s);
    float t[32];
    #pragma unroll
    for (int pass = 0; pass < 2; pass++) {
        unsigned long long zA[8], zB[8];
        #pragma unroll
        for (int j = 0; j < 8; j++) { zA[j] = 0ULL; zB[j] = 0ULL; }
        #pragma unroll
        for (int e = 0; e < 16; e++) {
            unsigned long long pceA = pk2(ceA[e], ceA[e]);
            unsigned long long pceB = pk2(ceB[e], ceB[e]);
            #pragma unroll
            for (int j4 = 0; j4 < 4; j4++) {
                ulonglong2 wv = suM[e * 8 + pass * 4 + j4];
                ffma2(zA[2 * j4], pceA, wv.x);
                ffma2(zA[2 * j4 + 1], pceA, wv.y);
                ffma2(zB[2 * j4], pceB, wv.x);
                ffma2(zB[2 * j4 + 1], pceB, wv.y);
            }
        }
        #pragma unroll
        for (int j = 0; j < 8; j++) {
            unsigned long long bb = b2p[pass * 8 + j];
            fadd2(zA[j], bb);
            fadd2(zB[j], bb);
            float la, ha, lb, hb;
            upk2(zA[j], la, ha);
            upk2(zB[j], lb, hb);
            t[pass * 16 + 2 * j]     = fmaxf(la, 0.f) + fmaxf(lb, 0.f);
            t[pass * 16 + 2 * j + 1] = fmaxf(ha, 0.f) + fmaxf(hb, 0.f);
        }
    }

    // ---- butterfly-sum over the 4 lanes of the loop group; mean ----
    #pragma unroll
    for (int st = 0; st < 2; st++) {
        int mask = 1 << st;  // 1,2 — stays within each 4-lane loop group
        #pragma unroll
        for (int o = 0; o < 32; o++) t[o] += __shfl_xor_sync(0xffffffffu, t[o], mask);
    }
    unsigned long long t2[16];
    #pragma unroll
    for (int j = 0; j < 16; j++) t2[j] = pk2(t[2 * j] * 0.125f, t[2 * j + 1] * 0.125f);

    // ---- fco: each of 4 lanes computes 8 outputs (packed, swizzled smem) ----
    const ulonglong2* sf = reinterpret_cast<const ulonglong2*>(s_fcw);
    float r[8];
    #pragma unroll
    for (int jj = 0; jj < 8; jj++) {
        int o2 = lj * 8 + jj;
        int key = FKEY(o2);
        unsigned long long acc = 0ULL;
        #pragma unroll
        for (int k4 = 0; k4 < 8; k4++) {
            ulonglong2 wv = sf[o2 * 8 + (k4 ^ key)];
            ffma2(acc, t2[2 * k4], wv.x);
            ffma2(acc, t2[2 * k4 + 1], wv.y);
        }
        float lo, hi;
        upk2(acc, lo, hi);
        r[jj] = lo + hi + s_fcb[o2];
    }

    long long lg = (long long)blockIdx.x * LPB + ll;
    if (lg < B) {
        float4* o4 = reinterpret_cast<float4*>(out);
        o4[lg * 8 + lj * 2]     = make_float4(r[0], r[1], r[2], r[3]);
        o4[lg * 8 + lj * 2 + 1] = make_float4(r[4], r[5], r[6], r[7]);
    }
}

// ---------------- launch ----------------
extern "C" void kernel_launch(void* const* d_in, const int* in_sizes, int n_in,
                              void* d_out, int out_size) {
    const float* node_features = (const float*)d_in[0];
    const void*  stroke_to_loop = d_in[1];
    const float* fc1_w = (const float*)d_in[2];
    const float* fc1_b = (const float*)d_in[3];
    const float* fc2_w = (const float*)d_in[4];
    const float* fc2_b = (const float*)d_in[5];
    const float* in_proj_w = (const float*)d_in[6];
    const float* in_proj_b = (const float*)d_in[7];
    const float* out_proj_w = (const float*)d_in[8];
    const float* out_proj_b = (const float*)d_in[9];
    const float* fc_w = (const float*)d_in[10];
    const float* fc_b = (const float*)d_in[11];
    const float* fco_w = (const float*)d_in[12];
    const float* fco_b = (const float*)d_in[13];

    int N = in_sizes[0] / 6;
    int B = in_sizes[1] / 8;

    k_node<<<(N + 127) / 128, 128>>>(node_features, fc1_w, fc1_b, fc2_w, fc2_b,
                                     in_proj_w, in_proj_b,
                                     fc_w, out_proj_w, out_proj_b, fc_b,
                                     (const int*)stroke_to_loop, N);
    k_loops<<<(B + LPB - 1) / LPB, 128>>>(stroke_to_loop, fco_w, fco_b, (float*)d_out, B);
}

// round 5
// speedup vs baseline: 3.2424x; 1.1059x over previous
#include <cuda_runtime.h>
#include <cstdint>

#define NMAX 100000
#define GREC 12            // float4 chunks per node record (48 floats: q,k,v)
#define LPB  32            // loops per block in k_loops (4 threads per loop)

// Scratch (static __device__ — no runtime allocation)
__device__ float4 g_pre[(size_t)NMAX * GREC];   // per-node: q*invsqrt8[16], k[16], v[16]
__device__ float  g_Mt[16 * 32];                // (fc_w @ out_proj_w)^T : [e][o]
__device__ float  g_b32[32];                    // fc_w @ out_proj_b + fc_b
__device__ int    g_idx64;                      // 1 if stroke_to_loop is int64

// Constant-memory mirrors (filled by async D2D copies after k_node; warp-uniform
// immediate-indexed reads go through the uniform/constant port, NOT L1)
__constant__ __align__(16) float c_Mt[16 * 32];
__constant__ __align__(16) float c_b32[32];
__constant__ __align__(16) float c_fcb[32];

// chunk swizzle inside a slot: key distinct across the 8 loop-groups of a warp
#define SKEY(slot) (((slot) ^ ((slot) >> 3)) & 7)
// fco row swizzle: key distinct over the 4 lanes of a loop group
#define FKEY(o) (((o) >> 3) & 3)

__device__ __forceinline__ int fetch_idx(const void* p, long long i, int is64) {
    if (is64) return (int)__ldg((const long long*)p + i);
    return __ldg((const int*)p + i);
}
__device__ __forceinline__ unsigned long long pk2(float lo, float hi) {
    unsigned long long r;
    asm("mov.b64 %0, {%1, %2};" : "=l"(r) : "f"(lo), "f"(hi));
    return r;
}
__device__ __forceinline__ void upk2(unsigned long long v, float& lo, float& hi) {
    asm("mov.b64 {%0, %1}, %2;" : "=f"(lo), "=f"(hi) : "l"(v));
}
__device__ __forceinline__ void ffma2(unsigned long long& d, unsigned long long a, unsigned long long b) {
    asm("fma.rn.f32x2 %0, %1, %2, %0;" : "+l"(d) : "l"(a), "l"(b));
}
__device__ __forceinline__ void fadd2(unsigned long long& d, unsigned long long a) {
    asm("add.rn.f32x2 %0, %1, %0;" : "+l"(d) : "l"(a));
}
__device__ __forceinline__ void cpa16(uint32_t dst_smem, const void* src) {
    asm volatile("cp.async.cg.shared.global [%0], [%1], 16;" :: "r"(dst_smem), "l"(src));
}

// ---------------- Kernel 1: per-node precompute (+ fused prep in block 0) ----------------
__global__ void __launch_bounds__(128)
k_node(const float* __restrict__ nf,
       const float* __restrict__ w1, const float* __restrict__ b1,
       const float* __restrict__ w2, const float* __restrict__ b2,
       const float* __restrict__ wp, const float* __restrict__ bp,
       const float* __restrict__ fc_w, const float* __restrict__ opw,
       const float* __restrict__ opb, const float* __restrict__ fc_b,
       const int* __restrict__ idx_raw, int N) {
    __shared__ __align__(16) float s_w1[256];   // [32][8] padded rows
    __shared__ __align__(16) float s_w2[512];   // [16][32]
    __shared__ __align__(16) float s_wp[768];   // [48][16]
    __shared__ float s_b1[32], s_b2[16], s_bp[48];
    __shared__ int s_flag;

    const int tid = threadIdx.x;

    if (blockIdx.x == 0) {
        if (tid == 0) s_flag = 0;
        #pragma unroll
        for (int i = tid; i < 512; i += 128) {
            int o = i >> 4, e = i & 15;
            float acc = 0.f;
            #pragma unroll
            for (int j = 0; j < 16; j++) acc += __ldg(fc_w + o * 16 + j) * __ldg(opw + j * 16 + e);
            g_Mt[e * 32 + o] = acc;
        }
        if (tid < 32) {
            float acc = __ldg(fc_b + tid);
            #pragma unroll
            for (int j = 0; j < 16; j++) acc += __ldg(fc_w + tid * 16 + j) * __ldg(opb + j);
            g_b32[tid] = acc;
        }
        __syncthreads();
        if (tid < 128 && __ldg(idx_raw + 2 * tid + 1) != 0) atomicOr(&s_flag, 1);
        __syncthreads();
        if (tid == 0) g_idx64 = (s_flag == 0) ? 1 : 0;
    }

    #pragma unroll
    for (int i = tid; i < 256; i += 128) {
        int o = i >> 3, c = i & 7;
        s_w1[i] = (c < 6) ? __ldg(w1 + o * 6 + c) : 0.f;
    }
    #pragma unroll
    for (int i = tid; i < 512; i += 128) s_w2[i] = __ldg(w2 + i);
    #pragma unroll
    for (int i = tid; i < 768; i += 128) s_wp[i] = __ldg(wp + i);
    if (tid < 32) s_b1[tid] = __ldg(b1 + tid);
    if (tid < 16) s_b2[tid] = __ldg(b2 + tid);
    if (tid < 48) s_bp[tid] = __ldg(bp + tid);
    __syncthreads();

    int n = blockIdx.x * 128 + tid;
    if (n >= N) return;

    float f[6];
    #pragma unroll
    for (int i = 0; i < 6; i++) f[i] = __ldg(nf + (size_t)n * 6 + i);

    const float4* w1v = (const float4*)s_w1;
    float h[32];
    #pragma unroll
    for (int o = 0; o < 32; o++) {
        float4 a = w1v[o * 2], b = w1v[o * 2 + 1];
        float acc = s_b1[o] + a.x * f[0] + a.y * f[1] + a.z * f[2] + a.w * f[3]
                  + b.x * f[4] + b.y * f[5];
        h[o] = fmaxf(acc, 0.f);
    }
    const float4* w2v = (const float4*)s_w2;
    float x[16];
    #pragma unroll
    for (int e = 0; e < 16; e++) {
        float acc = s_b2[e];
        #pragma unroll
        for (int j = 0; j < 8; j++) {
            float4 w = w2v[e * 8 + j];
            acc += w.x * h[4 * j] + w.y * h[4 * j + 1] + w.z * h[4 * j + 2] + w.w * h[4 * j + 3];
        }
        x[e] = acc;
    }
    const float4* wpv = (const float4*)s_wp;
    float qkv[48];
    #pragma unroll
    for (int o = 0; o < 48; o++) {
        float acc = s_bp[o];
        #pragma unroll
        for (int j = 0; j < 4; j++) {
            float4 w = wpv[o * 4 + j];
            acc += w.x * x[4 * j] + w.y * x[4 * j + 1] + w.z * x[4 * j + 2] + w.w * x[4 * j + 3];
        }
        qkv[o] = acc;
    }

    float4* rec4 = g_pre + (size_t)n * GREC;
    const float s = 0.3535533905932738f;  // 1/sqrt(8) folded into q
    #pragma unroll
    for (int j = 0; j < 4; j++)
        rec4[j] = make_float4(qkv[4 * j] * s, qkv[4 * j + 1] * s, qkv[4 * j + 2] * s, qkv[4 * j + 3] * s);
    #pragma unroll
    for (int j = 0; j < 8; j++)
        rec4[4 + j] = make_float4(qkv[16 + 4 * j], qkv[17 + 4 * j], qkv[18 + 4 * j], qkv[19 + 4 * j]);
}

// ---------------- Kernel 2: per-loop attention + epilogue ----------------
// 32 loops/block, 4 threads/loop, each thread handles query rows {j, j+4}.
__global__ void __launch_bounds__(128)
k_loops(const void* __restrict__ s2l,
        const float* __restrict__ fco_w,
        float* __restrict__ out, int B) {
    __shared__ __align__(16) float4 s_rec[LPB * 8 * 8];    // 32 KB: k[16]+v[16] per slot, swizzled
    __shared__ __align__(16) float4 s_fcw[256];            // 4 KB, row-swizzled
    __shared__ int    s_idx[LPB * 8];

    const int tid = threadIdx.x;
    const long long base8 = (long long)blockIdx.x * (LPB * 8);
    const long long total8 = (long long)B * 8;
    const int is64 = g_idx64;

    // ---- phase A: indices + fco weights ----
    #pragma unroll
    for (int i = 0; i < 2; i++) {
        long long gi = base8 + tid + i * 128;
        if (gi >= total8) gi = 0;
        s_idx[tid + i * 128] = fetch_idx(s2l, gi, is64);
    }
    const float4* fcw4 = (const float4*)fco_w;   // [32 rows][8 float4]
    #pragma unroll
    for (int i = tid; i < 256; i += 128) {
        int r = i >> 3, k4 = i & 7;
        s_fcw[r * 8 + (k4 ^ FKEY(r))] = __ldg(fcw4 + i);
    }
    __syncthreads();

    const int ll = tid >> 2;       // loop within block (0..31)
    const int lj = tid & 3;        // lane within loop; query rows lj and lj+4
    const int slotA = ll * 8 + lj;
    const int slotB = slotA + 4;

    // ---- own q rows from L2 ----
    unsigned long long q2A[8], q2B[8];
    {
        const ulonglong2* gq = reinterpret_cast<const ulonglong2*>(g_pre + (size_t)s_idx[slotA] * GREC);
        ulonglong2 a = __ldg(gq), b = __ldg(gq + 1), c = __ldg(gq + 2), d = __ldg(gq + 3);
        q2A[0] = a.x; q2A[1] = a.y; q2A[2] = b.x; q2A[3] = b.y;
        q2A[4] = c.x; q2A[5] = c.y; q2A[6] = d.x; q2A[7] = d.y;
    }
    {
        const ulonglong2* gq = reinterpret_cast<const ulonglong2*>(g_pre + (size_t)s_idx[slotB] * GREC);
        ulonglong2 a = __ldg(gq), b = __ldg(gq + 1), c = __ldg(gq + 2), d = __ldg(gq + 3);
        q2B[0] = a.x; q2B[1] = a.y; q2B[2] = b.x; q2B[3] = b.y;
        q2B[4] = c.x; q2B[5] = c.y; q2B[6] = d.x; q2B[7] = d.y;
    }

    // ---- phase B: cp.async stage k+v for all 256 slots (swizzled) ----
    {
        const int c = tid & 7, sb = tid >> 3;   // 16 slot-groups
        #pragma unroll
        for (int it = 0; it < 16; it++) {
            int slot = it * 16 + sb;
            int node = s_idx[slot];
            uint32_t dst = (uint32_t)__cvta_generic_to_shared(&s_rec[slot * 8 + (c ^ SKEY(slot))]);
            cpa16(dst, g_pre + (size_t)node * GREC + 4 + c);
        }
        asm volatile("cp.async.commit_group;");
        asm volatile("cp.async.wait_group 0;");
    }
    __syncthreads();

    const ulonglong2* su = reinterpret_cast<const ulonglong2*>(s_rec);

    // ---- scores (both heads, both rows); k tiles shared across the 2 rows ----
    float p0A[8], p1A[8], p0B[8], p1B[8];
    #pragma unroll
    for (int m = 0; m < 8; m++) {
        int sm = ll * 8 + m;
        int key = SKEY(sm);
        int base = sm * 8;
        ulonglong2 k0 = su[base + (0 ^ key)];
        ulonglong2 k1 = su[base + (1 ^ key)];
        ulonglong2 k2 = su[base + (2 ^ key)];
        ulonglong2 k3 = su[base + (3 ^ key)];
        unsigned long long a0 = 0ULL, a1 = 0ULL, b0 = 0ULL, b1 = 0ULL;
        ffma2(a0, q2A[0], k0.x); ffma2(a0, q2A[1], k0.y);
        ffma2(a0, q2A[2], k1.x); ffma2(a0, q2A[3], k1.y);
        ffma2(a1, q2A[4], k2.x); ffma2(a1, q2A[5], k2.y);
        ffma2(a1, q2A[6], k3.x); ffma2(a1, q2A[7], k3.y);
        ffma2(b0, q2B[0], k0.x); ffma2(b0, q2B[1], k0.y);
        ffma2(b0, q2B[2], k1.x); ffma2(b0, q2B[3], k1.y);
        ffma2(b1, q2B[4], k2.x); ffma2(b1, q2B[5], k2.y);
        ffma2(b1, q2B[6], k3.x); ffma2(b1, q2B[7], k3.y);
        float lo, hi;
        upk2(a0, lo, hi); p0A[m] = lo + hi;
        upk2(a1, lo, hi); p1A[m] = lo + hi;
        upk2(b0, lo, hi); p0B[m] = lo + hi;
        upk2(b1, lo, hi); p1B[m] = lo + hi;
    }

    // ---- softmax over m, per head, per row ----
    {
        float mx0 = p0A[0], mx1 = p1A[0], mx2 = p0B[0], mx3 = p1B[0];
        #pragma unroll
        for (int m = 1; m < 8; m++) {
            mx0 = fmaxf(mx0, p0A[m]); mx1 = fmaxf(mx1, p1A[m]);
            mx2 = fmaxf(mx2, p0B[m]); mx3 = fmaxf(mx3, p1B[m]);
        }
        float s0 = 0.f, s1 = 0.f, s2 = 0.f, s3 = 0.f;
        #pragma unroll
        for (int m = 0; m < 8; m++) {
            p0A[m] = __expf(p0A[m] - mx0); s0 += p0A[m];
            p1A[m] = __expf(p1A[m] - mx1); s1 += p1A[m];
            p0B[m] = __expf(p0B[m] - mx2); s2 += p0B[m];
            p1B[m] = __expf(p1B[m] - mx3); s3 += p1B[m];
        }
        float i0 = __frcp_rn(s0), i1 = __frcp_rn(s1), i2 = __frcp_rn(s2), i3 = __frcp_rn(s3);
        #pragma unroll
        for (int m = 0; m < 8; m++) {
            p0A[m] *= i0; p1A[m] *= i1; p0B[m] *= i2; p1B[m] *= i3;
        }
    }

    // ---- ctx for both rows; v tiles shared ----
    unsigned long long cxA[8], cxB[8];
    #pragma unroll
    for (int j = 0; j < 8; j++) { cxA[j] = 0ULL; cxB[j] = 0ULL; }
    #pragma unroll
    for (int m = 0; m < 8; m++) {
        int sm = ll * 8 + m;
        int key = SKEY(sm);
        int base = sm * 8;
        ulonglong2 v0 = su[base + (4 ^ key)];
        ulonglong2 v1 = su[base + (5 ^ key)];
        ulonglong2 v2 = su[base + (6 ^ key)];
        ulonglong2 v3 = su[base + (7 ^ key)];
        unsigned long long ppA0 = pk2(p0A[m], p0A[m]);
        unsigned long long ppA1 = pk2(p1A[m], p1A[m]);
        unsigned long long ppB0 = pk2(p0B[m], p0B[m]);
        unsigned long long ppB1 = pk2(p1B[m], p1B[m]);
        ffma2(cxA[0], ppA0, v0.x); ffma2(cxA[1], ppA0, v0.y);
        ffma2(cxA[2], ppA0, v1.x); ffma2(cxA[3], ppA0, v1.y);
        ffma2(cxA[4], ppA1, v2.x); ffma2(cxA[5], ppA1, v2.y);
        ffma2(cxA[6], ppA1, v3.x); ffma2(cxA[7], ppA1, v3.y);
        ffma2(cxB[0], ppB0, v0.x); ffma2(cxB[1], ppB0, v0.y);
        ffma2(cxB[2], ppB0, v1.x); ffma2(cxB[3], ppB0, v1.y);
        ffma2(cxB[4], ppB1, v2.x); ffma2(cxB[5], ppB1, v2.y);
        ffma2(cxB[6], ppB1, v3.x); ffma2(cxB[7], ppB1, v3.y);
    }
    float ceA[16], ceB[16];
    #pragma unroll
    for (int j = 0; j < 8; j++) {
        upk2(cxA[j], ceA[2 * j], ceA[2 * j + 1]);
        upk2(cxB[j], ceB[2 * j], ceB[2 * j + 1]);
    }

    // ---- z = Mt^T ctx for both rows via CONSTANT memory (uniform port, off L1) ----
    const unsigned long long* cM = reinterpret_cast<const unsigned long long*>(c_Mt);
    const unsigned long long* cB = reinterpret_cast<const unsigned long long*>(c_b32);
    float t[32];
    #pragma unroll
    for (int pass = 0; pass < 2; pass++) {
        unsigned long long zA[8], zB[8];
        #pragma unroll
        for (int j = 0; j < 8; j++) { zA[j] = 0ULL; zB[j] = 0ULL; }
        #pragma unroll
        for (int e = 0; e < 16; e++) {
            unsigned long long pceA = pk2(ceA[e], ceA[e]);
            unsigned long long pceB = pk2(ceB[e], ceB[e]);
            #pragma unroll
            for (int j2 = 0; j2 < 8; j2++) {
                unsigned long long wv = cM[e * 16 + pass * 8 + j2];  // immediate offsets
                ffma2(zA[j2], pceA, wv);
                ffma2(zB[j2], pceB, wv);
            }
        }
        #pragma unroll
        for (int j = 0; j < 8; j++) {
            unsigned long long bb = cB[pass * 8 + j];
            fadd2(zA[j], bb);
            fadd2(zB[j], bb);
            float la, ha, lb, hb;
            upk2(zA[j], la, ha);
            upk2(zB[j], lb, hb);
            t[pass * 16 + 2 * j]     = fmaxf(la, 0.f) + fmaxf(lb, 0.f);
            t[pass * 16 + 2 * j + 1] = fmaxf(ha, 0.f) + fmaxf(hb, 0.f);
        }
    }

    // ---- butterfly-sum over the 4 lanes of the loop group; mean ----
    #pragma unroll
    for (int st = 0; st < 2; st++) {
        int mask = 1 << st;  // 1,2 — stays within each 4-lane loop group
        #pragma unroll
        for (int o = 0; o < 32; o++) t[o] += __shfl_xor_sync(0xffffffffu, t[o], mask);
    }
    unsigned long long t2[16];
    #pragma unroll
    for (int j = 0; j < 16; j++) t2[j] = pk2(t[2 * j] * 0.125f, t[2 * j + 1] * 0.125f);

    // ---- fco: each of 4 lanes computes 8 outputs (packed, swizzled smem) ----
    const ulonglong2* sf = reinterpret_cast<const ulonglong2*>(s_fcw);
    float r[8];
    #pragma unroll
    for (int jj = 0; jj < 8; jj++) {
        int o2 = lj * 8 + jj;
        int key = FKEY(o2);
        unsigned long long acc = 0ULL;
        #pragma unroll
        for (int k4 = 0; k4 < 8; k4++) {
            ulonglong2 wv = sf[o2 * 8 + (k4 ^ key)];
            ffma2(acc, t2[2 * k4], wv.x);
            ffma2(acc, t2[2 * k4 + 1], wv.y);
        }
        float lo, hi;
        upk2(acc, lo, hi);
        r[jj] = lo + hi + c_fcb[o2];
    }

    long long lg = (long long)blockIdx.x * LPB + ll;
    if (lg < B) {
        float4* o4 = reinterpret_cast<float4*>(out);
        o4[lg * 8 + lj * 2]     = make_float4(r[0], r[1], r[2], r[3]);
        o4[lg * 8 + lj * 2 + 1] = make_float4(r[4], r[5], r[6], r[7]);
    }
}

// ---------------- launch ----------------
extern "C" void kernel_launch(void* const* d_in, const int* in_sizes, int n_in,
                              void* d_out, int out_size) {
    const float* node_features = (const float*)d_in[0];
    const void*  stroke_to_loop = d_in[1];
    const float* fc1_w = (const float*)d_in[2];
    const float* fc1_b = (const float*)d_in[3];
    const float* fc2_w = (const float*)d_in[4];
    const float* fc2_b = (const float*)d_in[5];
    const float* in_proj_w = (const float*)d_in[6];
    const float* in_proj_b = (const float*)d_in[7];
    const float* out_proj_w = (const float*)d_in[8];
    const float* out_proj_b = (const float*)d_in[9];
    const float* fc_w = (const float*)d_in[10];
    const float* fc_b = (const float*)d_in[11];
    const float* fco_w = (const float*)d_in[12];
    const float* fco_b = (const float*)d_in[13];

    int N = in_sizes[0] / 6;
    int B = in_sizes[1] / 8;

    k_node<<<(N + 127) / 128, 128>>>(node_features, fc1_w, fc1_b, fc2_w, fc2_b,
                                     in_proj_w, in_proj_b,
                                     fc_w, out_proj_w, out_proj_b, fc_b,
                                     (const int*)stroke_to_loop, N);

    // stream-ordered D2D copies of the folded weights into constant memory
    void* gMt_addr = nullptr; void* gb32_addr = nullptr;
    cudaGetSymbolAddress(&gMt_addr, g_Mt);
    cudaGetSymbolAddress(&gb32_addr, g_b32);
    cudaMemcpyToSymbolAsync(c_Mt, gMt_addr, 512 * sizeof(float), 0,
                            cudaMemcpyDeviceToDevice, 0);
    cudaMemcpyToSymbolAsync(c_b32, gb32_addr, 32 * sizeof(float), 0,
                            cudaMemcpyDeviceToDevice, 0);
    cudaMemcpyToSymbolAsync(c_fcb, fco_b, 32 * sizeof(float), 0,
                            cudaMemcpyDeviceToDevice, 0);

    k_loops<<<(B + LPB - 1) / LPB, 128>>>(stroke_to_loop, fco_w, (float*)d_out, B);
}